// round 15
// baseline (speedup 1.0000x reference)
#include <cuda_runtime.h>
#include <cuda_fp16.h>
#include <math.h>

// Problem constants
#define BB   16
#define CC   256
#define OO   256
#define HH   32
#define WW   32
#define EE   4
#define CR   16
#define GG   8
#define CPG  32
#define HWSZ 1024
#define EPSV 1e-5f

#define PADW 34
#define PADPX (PADW * PADW)
#define NTILE 256                   // 16x16 winograd tiles per image
#define NSTG 4
#define TILE_A 16384                // 128 rows x 128B (K=64 fp16)
#define TILE_B 32768                // 256 rows x 128B
#define STAGE_BYTES (TILE_A + TILE_B)
#define SMEM_TOTAL (NSTG * STAGE_BYTES)   // 196608

// ---------------- scratch ----------------------------------------------------
__device__ float  g_pooled[BB * CC];
__device__ float  g_gate[BB * EE];
__device__ int    g_actlist[BB * EE];
__device__ int    g_nact;
__device__ __half g_xT[(size_t)BB * PADPX * CC];             // padded px-major fp16
__device__ __half g_swT[OO * CC];                            // shared 1x1 weights fp16
__device__ __half g_V[(size_t)BB * 16 * NTILE * CC];         // input winograd transform
__device__ __half g_U[(size_t)EE * 16 * OO * CC];            // weight winograd transform
__device__ __half g_M[(size_t)32 * 16 * OO * NTILE];         // per-active-pair products
__device__ __half g_shared_raw[(size_t)BB * OO * HWSZ];      // fp16 raw conv outputs
__device__ __half g_expert_raw[(size_t)BB * EE * OO * HWSZ]; // fp16 raw conv outputs
// GN partials for SHARED only: [b 0..15][group][warp_m 0..3][px_tile 0..7]
__device__ float  g_psum[BB * GG * 4 * 8];
__device__ float  g_psq [BB * GG * 4 * 8];
__device__ float  g_sh_mean[BB * GG], g_sh_rstd[BB * GG];
__device__ float  g_ex_mean[BB * EE * GG], g_ex_rstd[BB * EE * GG];

// ---------------- helpers ----------------------------------------------------
__device__ __forceinline__ float warpsum(float v) {
    #pragma unroll
    for (int o = 16; o > 0; o >>= 1) v += __shfl_down_sync(0xffffffffu, v, o);
    return v;
}
__device__ __forceinline__ float silu(float v) { return v / (1.0f + expf(-v)); }

__device__ __forceinline__ unsigned smem_u32(const void* p) {
    unsigned a;
    asm("{ .reg .u64 t; cvta.to.shared.u64 t, %1; cvt.u32.u64 %0, t; }" : "=r"(a) : "l"(p));
    return a;
}
__device__ __forceinline__ void cp16(unsigned dst, const void* src) {
    asm volatile("cp.async.cg.shared.global [%0], [%1], 16;" :: "r"(dst), "l"(src));
}
__device__ __forceinline__ void cp_commit() { asm volatile("cp.async.commit_group;"); }

__device__ __forceinline__ void ldm4(unsigned& r0, unsigned& r1, unsigned& r2, unsigned& r3,
                                     unsigned addr) {
    asm volatile("ldmatrix.sync.aligned.m8n8.x4.shared.b16 {%0,%1,%2,%3}, [%4];"
                 : "=r"(r0), "=r"(r1), "=r"(r2), "=r"(r3) : "r"(addr));
}

__device__ __forceinline__ void mma_f16(float* c, unsigned a0, unsigned a1, unsigned a2, unsigned a3,
                                        unsigned b0, unsigned b1) {
    asm volatile(
        "mma.sync.aligned.m16n8k16.row.col.f32.f16.f16.f32 "
        "{%0,%1,%2,%3}, {%4,%5,%6,%7}, {%8,%9}, {%0,%1,%2,%3};"
        : "+f"(c[0]), "+f"(c[1]), "+f"(c[2]), "+f"(c[3])
        : "r"(a0), "r"(a1), "r"(a2), "r"(a3), "r"(b0), "r"(b1));
}

// ---------------- K1: router (+ active list) -----------------------------------
__global__ void router_kernel(const float* __restrict__ w1, const float* __restrict__ b1,
                              const float* __restrict__ w2, const float* __restrict__ b2) {
    __shared__ float hs[BB][CR];
    __shared__ float lg[BB][EE];
    int tid = threadIdx.x;
    {
        int b = tid / CR, j = tid % CR;
        float s = b1[j];
        const float* wr = w1 + j * CC;
        const float* pr = g_pooled + b * CC;
        for (int c = 0; c < CC; c++) s = fmaf(wr[c], pr[c], s);
        hs[b][j] = silu(s);
    }
    __syncthreads();
    if (tid < BB * EE) {
        int b = tid / EE, e = tid % EE;
        float s = b2[e];
        for (int j = 0; j < CR; j++) s = fmaf(w2[e * CR + j], hs[b][j], s);
        lg[b][e] = s;
    }
    __syncthreads();
    if (tid < BB) {
        int b = tid;
        float m = lg[b][0];
        for (int e = 1; e < EE; e++) m = fmaxf(m, lg[b][e]);
        float p[EE]; float Z = 0.f;
        for (int e = 0; e < EE; e++) { p[e] = expf(lg[b][e] - m); Z += p[e]; }
        for (int e = 0; e < EE; e++) p[e] /= Z;
        int i1 = 0;
        for (int e = 1; e < EE; e++) if (p[e] > p[i1]) i1 = e;
        int i2 = -1;
        for (int e = 0; e < EE; e++) {
            if (e == i1) continue;
            if (i2 < 0 || p[e] > p[i2]) i2 = e;
        }
        float v1 = p[i1], v2 = p[i2], sum = v1 + v2;
        float wA = v1 / sum, wB = v2 / sum;
        if (wA < 0.01f) wA = 0.f;
        if (wB < 0.01f) wB = 0.f;
        for (int e = 0; e < EE; e++) g_gate[b * EE + e] = 0.f;
        g_gate[b * EE + i1] = wA;
        g_gate[b * EE + i2] = wB;
    }
    __syncthreads();
    if (tid == 0) {
        int n = 0;
        for (int be = 0; be < BB * EE; be++)
            if (g_gate[be] != 0.f) g_actlist[n++] = be;
        g_nact = n;
    }
}

// ---------------- K0: fused prep (xt + swt + pool), fp16 -----------------------
// blocks [0,544): x transpose; [544,800): shared w; [800,1312): pool
__global__ void prep_kernel(const float* __restrict__ x, const float* __restrict__ sw) {
    int bid = blockIdx.x;
    int tid = threadIdx.x;
    if (bid < 544) {
        int b = bid / 34;
        int hp = bid % 34;
        int h = hp - 1;
        __half* outrow = g_xT + ((size_t)b * PADPX + (size_t)hp * PADW) * CC;
        const __half hz = __float2half_rn(0.f);
        if (h < 0 || h >= HH) {
            for (int i = tid; i < PADW * CC; i += 256) outrow[i] = hz;
            return;
        }
        outrow[tid] = hz;
        outrow[33 * CC + tid] = hz;
        __shared__ float s[CC][33];
        for (int i = tid; i < CC * WW; i += 256) {
            int c = i >> 5, w = i & 31;
            s[c][w] = x[((size_t)(b * CC + c)) * HWSZ + h * WW + w];
        }
        __syncthreads();
        for (int i = tid; i < WW * CC; i += 256) {
            int w = i >> 8, c = i & 255;
            outrow[(size_t)(w + 1) * CC + c] = __float2half_rn(s[c][w]);
        }
    } else if (bid < 800) {
        int idx = (bid - 544) * 256 + tid;          // o*256 + c
        int c = idx & 255, o = idx >> 8;
        g_swT[(o << 8) + c] = __float2half_rn(sw[idx]);
    } else {
        int warp = tid >> 5, lane = tid & 31;
        int idx = (bid - 800) * 8 + warp;           // b*CC + c
        const float* p = x + (size_t)idx * HWSZ;
        float s = 0.f;
        for (int i = lane; i < HWSZ; i += 32) s += p[i];
        s = warpsum(s);
        if (lane == 0) g_pooled[idx] = s * (1.0f / HWSZ);
    }
}

// ---------------- K2a: input winograd transform V = B^T d B --------------------
// grid 256 (b*16 + th); threads = 256 (one per channel c)
__global__ void vtrans_kernel() {
    int bid = blockIdx.x;
    int b = bid >> 4, th = bid & 15;
    int c = threadIdx.x;
    const __half* xb = g_xT + ((size_t)b * PADPX) * CC + c;
    __half* vb = g_V + ((size_t)b * 16) * NTILE * CC;
    for (int tw = 0; tw < 16; tw++) {
        float d[4][4];
        #pragma unroll
        for (int i = 0; i < 4; i++)
            #pragma unroll
            for (int j = 0; j < 4; j++)
                d[i][j] = __half2float(xb[((size_t)(2 * th + i) * PADW + 2 * tw + j) * CC]);
        float z[4][4];
        #pragma unroll
        for (int j = 0; j < 4; j++) {
            z[0][j] = d[0][j] - d[2][j];
            z[1][j] = d[1][j] + d[2][j];
            z[2][j] = d[2][j] - d[1][j];
            z[3][j] = d[1][j] - d[3][j];
        }
        int t = th * 16 + tw;
        #pragma unroll
        for (int i = 0; i < 4; i++) {
            float v0 = z[i][0] - z[i][2];
            float v1 = z[i][1] + z[i][2];
            float v2 = z[i][2] - z[i][1];
            float v3 = z[i][1] - z[i][3];
            vb[((size_t)(i * 4 + 0) * NTILE + t) * CC + c] = __float2half_rn(v0);
            vb[((size_t)(i * 4 + 1) * NTILE + t) * CC + c] = __float2half_rn(v1);
            vb[((size_t)(i * 4 + 2) * NTILE + t) * CC + c] = __float2half_rn(v2);
            vb[((size_t)(i * 4 + 3) * NTILE + t) * CC + c] = __float2half_rn(v3);
        }
    }
}

// ---------------- K2b: weight winograd transform U = G g G^T -------------------
// grid 1024 (e*256 + o); threads 256 (c); smem-staged contiguous weight reads
__global__ void utrans_kernel(const float* __restrict__ ew) {
    __shared__ float s[CC * 9];
    int bid = blockIdx.x;
    int e = bid >> 8, o = bid & 255;
    int tid = threadIdx.x;
    const float* src = ew + ((size_t)(e * OO + o)) * CC * 9;
    for (int i = tid; i < CC * 9; i += 256) s[i] = src[i];
    __syncthreads();
    int c = tid;
    float g0[3], g1[3], g2[3];
    #pragma unroll
    for (int j = 0; j < 3; j++) {
        g0[j] = s[c * 9 + 0 + j];
        g1[j] = s[c * 9 + 3 + j];
        g2[j] = s[c * 9 + 6 + j];
    }
    float zg[4][3];
    #pragma unroll
    for (int j = 0; j < 3; j++) {
        zg[0][j] = g0[j];
        zg[1][j] = 0.5f * (g0[j] + g1[j] + g2[j]);
        zg[2][j] = 0.5f * (g0[j] - g1[j] + g2[j]);
        zg[3][j] = g2[j];
    }
    __half* ub = g_U + ((size_t)e * 16) * OO * CC;
    #pragma unroll
    for (int i = 0; i < 4; i++) {
        float u0 = zg[i][0];
        float u1 = 0.5f * (zg[i][0] + zg[i][1] + zg[i][2]);
        float u2 = 0.5f * (zg[i][0] - zg[i][1] + zg[i][2]);
        float u3 = zg[i][2];
        ub[((size_t)(i * 4 + 0) * OO + o) * CC + c] = __float2half_rn(u0);
        ub[((size_t)(i * 4 + 1) * OO + o) * CC + c] = __float2half_rn(u1);
        ub[((size_t)(i * 4 + 2) * OO + o) * CC + c] = __float2half_rn(u2);
        ub[((size_t)(i * 4 + 3) * OO + o) * CC + c] = __float2half_rn(u3);
    }
}

// ---------------- K3: fp16 warp-MMA GEMM (uniform 4-iter CTAs) -----------------
// flat grid 1152: id<1024 expert winograd (apair,uv,mtile); id>=1024 shared conv.
// CTA tile 128(M) x 256(N); warp grid 4(M) x 8(N); warp tile 32x32 (m16n8k16).
__global__ void __launch_bounds__(1024, 1)
gemm_kernel() {
    extern __shared__ char smem[];
    unsigned sb = smem_u32(smem);
    int tid = threadIdx.x, warp = tid >> 5, lane = tid & 31;
    int warp_m = warp >> 3, warp_n = warp & 7;
    int g = lane >> 2, q = lane & 3;

    int id = blockIdx.x;
    bool is_shared = (id >= 1024);
    const __half *aSrcBase, *bSrcBase;
    __half* outp;
    int out_stride, out_col, slot_b = 0, pxtile = 0;
    if (is_shared) {
        int sid = id - 1024;
        int b = sid >> 3;
        pxtile = sid & 7;
        int p0 = pxtile * 128;
        int arow = tid >> 3, aq = tid & 7;
        int p = p0 + arow;
        int ppad = ((p >> 5) + 1) * PADW + (p & 31) + 1;
        aSrcBase = g_xT + ((size_t)b * PADPX + ppad) * CC + aq * 8;
        int brow = tid >> 2, bh = tid & 3;
        bSrcBase = g_swT + ((size_t)brow << 8) + bh * 16;
        outp = g_shared_raw + (size_t)b * OO * HWSZ;
        out_stride = HWSZ;
        out_col = p0;
        slot_b = b;
    } else {
        int apair = id >> 5;
        if (apair >= g_nact) return;
        int rem = id & 31;
        int uv = rem >> 1, t0 = (rem & 1) * 128;
        int be = g_actlist[apair];
        int b = be >> 2, e = be & 3;
        int arow = tid >> 3, aq = tid & 7;
        aSrcBase = g_V + (((size_t)b * 16 + uv) * NTILE + t0 + arow) * CC + aq * 8;
        int brow = tid >> 2, bh = tid & 3;
        bSrcBase = g_U + (((size_t)e * 16 + uv) * OO + brow) * CC + bh * 16;
        outp = g_M + (((size_t)apair * 16 + uv) * OO) * NTILE;
        out_stride = NTILE;
        out_col = t0;
    }

    int arow = tid >> 3, aq = tid & 7;
    int brow = tid >> 2, bh = tid & 3;
    unsigned xrA = (unsigned)(arow & 7) << 4;
    unsigned xrB = (unsigned)(brow & 7) << 4;
    unsigned aDstRow = sb + arow * 128;
    unsigned bDstRow = sb + TILE_A + brow * 128;
    unsigned aq16 = (unsigned)aq * 16, bh32 = (unsigned)bh * 32;

    auto load_stage = [&](int iter, int buf) {
        int c0 = iter << 6;
        const __half* as = aSrcBase + c0;
        const __half* bs = bSrcBase + c0;
        unsigned aDst = aDstRow + buf * STAGE_BYTES;
        unsigned bDst = bDstRow + buf * STAGE_BYTES;
        cp16(aDst + (aq16 ^ xrA), as);
        cp16(bDst + ((bh32)      ^ xrB), bs);
        cp16(bDst + ((bh32 + 16) ^ xrB), bs + 8);
        cp_commit();
    };

    unsigned l7 = lane & 7;
    unsigned key = l7 << 4;
    unsigned rsel = (((unsigned)lane >> 3) & 1u) * 8u;
    unsigned hsel = ((unsigned)lane >> 4) << 4;
    unsigned rowA = (unsigned)(warp_m * 32) + l7 + rsel;
    unsigned aOff = rowA * 128u;
    unsigned rowB = (unsigned)(warp_n * 32) + l7 + rsel;
    unsigned bOff = TILE_A + rowB * 128u;
    unsigned kphase = (unsigned)warp & 3u;

    float acc[2][4][4] = {};

    auto compute = [&](int buf) {
        unsigned base = sb + buf * STAGE_BYTES;
        #pragma unroll
        for (int ks0 = 0; ks0 < 4; ks0++) {
            unsigned kstep = ((unsigned)ks0 + kphase) & 3u;
            unsigned kb = ((kstep * 32u) + hsel) ^ key;
            unsigned a[2][4];
            #pragma unroll
            for (int mi = 0; mi < 2; mi++)
                ldm4(a[mi][0], a[mi][1], a[mi][2], a[mi][3],
                     base + aOff + mi * 2048u + kb);
            unsigned bf[2][4];
            #pragma unroll
            for (int j = 0; j < 2; j++)
                ldm4(bf[j][0], bf[j][1], bf[j][2], bf[j][3],
                     base + bOff + j * 2048u + kb);
            #pragma unroll
            for (int mi = 0; mi < 2; mi++) {
                #pragma unroll
                for (int j = 0; j < 2; j++) {
                    mma_f16(acc[mi][2 * j],     a[mi][0], a[mi][1], a[mi][2], a[mi][3],
                            bf[j][0], bf[j][2]);
                    mma_f16(acc[mi][2 * j + 1], a[mi][0], a[mi][1], a[mi][2], a[mi][3],
                            bf[j][1], bf[j][3]);
                }
            }
        }
    };

    // pipeline: NITER = 4 for every CTA
    load_stage(0, 0);
    load_stage(1, 1);
    asm volatile("cp.async.wait_group 0;" ::: "memory");
    __syncthreads();
    load_stage(2, 2);
    load_stage(3, 3);
    compute(0);
    compute(1);
    asm volatile("cp.async.wait_group 0;" ::: "memory");
    __syncthreads();
    compute(2);
    compute(3);

    // GN partials: SHARED only (expert stats come from outtrans)
    if (is_shared) {
        float s = 0.f, sq = 0.f;
        #pragma unroll
        for (int mi = 0; mi < 2; mi++)
            #pragma unroll
            for (int ni = 0; ni < 4; ni++)
                #pragma unroll
                for (int c = 0; c < 4; c++) {
                    float v = acc[mi][ni][c];
                    s += v;
                    sq = fmaf(v, v, sq);
                }
        s = warpsum(s); sq = warpsum(sq);
        if (lane == 0) {
            int idx = ((slot_b * GG + warp_n) * 4 + warp_m) * 8 + pxtile;
            g_psum[idx] = s;
            g_psq[idx]  = sq;
        }
    }
    __syncthreads();

    // epilogue: transpose through smem, fp16 coalesced stores
    float* T = (float*)smem;                      // 256 n-rows x stride 132
    #pragma unroll
    for (int mi = 0; mi < 2; mi++) {
        int m = warp_m * 32 + mi * 16 + g;
        #pragma unroll
        for (int ni = 0; ni < 4; ni++) {
            int n = warp_n * 32 + ni * 8 + 2 * q;
            T[n * 132 + m]           = acc[mi][ni][0];
            T[(n + 1) * 132 + m]     = acc[mi][ni][1];
            T[n * 132 + m + 8]       = acc[mi][ni][2];
            T[(n + 1) * 132 + m + 8] = acc[mi][ni][3];
        }
    }
    __syncthreads();

    #pragma unroll
    for (int rr = 0; rr < 8; rr++) {
        int n = warp * 8 + rr;
        float4 v = *(const float4*)(T + n * 132 + lane * 4);
        __half2 h01 = __floats2half2_rn(v.x, v.y);
        __half2 h23 = __floats2half2_rn(v.z, v.w);
        uint2 u;
        u.x = *(unsigned*)&h01;
        u.y = *(unsigned*)&h23;
        *(uint2*)(outp + (size_t)n * out_stride + out_col + lane * 4) = u;
    }
}

// ---------------- K4: GroupNorm finalize (shared only; warp per item) ----------
__global__ void finalize_kernel() {
    int warp = threadIdx.x >> 5, lane = threadIdx.x & 31;
    int item = blockIdx.x * 32 + warp;             // 0..127
    if (item >= BB * GG) return;
    int slot = item / GG, g = item % GG;
    int base = (slot * GG + g) * 32;
    float S = warpsum(g_psum[base + lane]);
    float Q = warpsum(g_psq[base + lane]);
    if (lane == 0) {
        const float inv = 1.0f / (CPG * HWSZ);
        float mean = S * inv;
        float var = Q * inv - mean * mean;
        g_sh_mean[slot * GG + g] = mean;
        g_sh_rstd[slot * GG + g] = rsqrtf(var + EPSV);
    }
}

// ---------------- K5: output winograd transform Y = A^T M A + expert GN stats --
// grid 256 (apair*8 + group); threads 256 (one per tile)
__global__ void outtrans_kernel() {
    int bid = blockIdx.x;
    int apair = bid >> 3, grp = bid & 7;
    if (apair >= g_nact) return;
    int be = g_actlist[apair];
    int t = threadIdx.x;
    int th = t >> 4, tw = t & 15;
    int row0 = (2 * th) * WW + 2 * tw;

    const __half* mb = g_M + ((size_t)apair * 16) * OO * NTILE;
    __half* outb = g_expert_raw + (size_t)be * OO * HWSZ;

    float s = 0.f, sq = 0.f;
    for (int ol = 0; ol < CPG; ol++) {
        int o = grp * CPG + ol;
        float M[16];
        #pragma unroll
        for (int uv = 0; uv < 16; uv++)
            M[uv] = __half2float(mb[((size_t)uv * OO + o) * NTILE + t]);
        float zm0[4], zm1[4];
        #pragma unroll
        for (int j = 0; j < 4; j++) {
            zm0[j] = M[0 * 4 + j] + M[1 * 4 + j] + M[2 * 4 + j];
            zm1[j] = M[1 * 4 + j] - M[2 * 4 + j] - M[3 * 4 + j];
        }
        float y00 = zm0[0] + zm0[1] + zm0[2];
        float y01 = zm0[1] - zm0[2] - zm0[3];
        float y10 = zm1[0] + zm1[1] + zm1[2];
        float y11 = zm1[1] - zm1[2] - zm1[3];
        s += y00 + y01 + y10 + y11;
        sq = fmaf(y00, y00, sq); sq = fmaf(y01, y01, sq);
        sq = fmaf(y10, y10, sq); sq = fmaf(y11, y11, sq);
        __half* po = outb + (size_t)o * HWSZ;
        *(__half2*)(po + row0)      = __floats2half2_rn(y00, y01);
        *(__half2*)(po + row0 + WW) = __floats2half2_rn(y10, y11);
    }
    s = warpsum(s); sq = warpsum(sq);
    __shared__ float ss[8], sqs[8];
    int warp = threadIdx.x >> 5, lane = threadIdx.x & 31;
    if (lane == 0) { ss[warp] = s; sqs[warp] = sq; }
    __syncthreads();
    if (threadIdx.x == 0) {
        float S = 0.f, Q = 0.f;
        #pragma unroll
        for (int i = 0; i < 8; i++) { S += ss[i]; Q += sqs[i]; }
        const float inv = 1.0f / (CPG * HWSZ);
        float mean = S * inv;
        float var = Q * inv - mean * mean;
        g_ex_mean[be * GG + grp] = mean;
        g_ex_rstd[be * GG + grp] = rsqrtf(var + EPSV);
    }
}

// ---------------- K6: normalize + SiLU + gated combine (half4 loads) -----------
__global__ void combine_kernel(const float* __restrict__ egam, const float* __restrict__ ebet,
                               const float* __restrict__ sgam, const float* __restrict__ sbet,
                               float* __restrict__ out) {
    size_t i4 = (size_t)blockIdx.x * 256 + threadIdx.x;
    size_t t = i4 >> 8;
    int o = (int)(t & 255);
    int b = (int)(t >> 8);
    int g = o >> 5;

    uint2 vv = ((const uint2*)g_shared_raw)[i4];
    __half2 v01 = *(__half2*)&vv.x, v23 = *(__half2*)&vv.y;
    float2 f01 = __half22float2(v01), f23 = __half22float2(v23);
    float m = g_sh_mean[b * GG + g], r = g_sh_rstd[b * GG + g];
    float ga = sgam[o], be_ = sbet[o];
    float4 res;
    res.x = silu(fmaf((f01.x - m) * r, ga, be_));
    res.y = silu(fmaf((f01.y - m) * r, ga, be_));
    res.z = silu(fmaf((f23.x - m) * r, ga, be_));
    res.w = silu(fmaf((f23.y - m) * r, ga, be_));

    #pragma unroll
    for (int e = 0; e < EE; e++) {
        float ge = g_gate[b * EE + e];
        if (ge != 0.f) {
            int beg = b * EE + e;
            size_t ei = ((size_t)beg * OO + o) * (HWSZ / 4) + (i4 & 255);
            uint2 ew2 = ((const uint2*)g_expert_raw)[ei];
            __half2 e01 = *(__half2*)&ew2.x, e23 = *(__half2*)&ew2.y;
            float2 g01 = __half22float2(e01), g23 = __half22float2(e23);
            float em = g_ex_mean[beg * GG + g], er = g_ex_rstd[beg * GG + g];
            float eg = egam[e * OO + o], eb = ebet[e * OO + o];
            res.x = fmaf(ge, silu(fmaf((g01.x - em) * er, eg, eb)), res.x);
            res.y = fmaf(ge, silu(fmaf((g01.y - em) * er, eg, eb)), res.y);
            res.z = fmaf(ge, silu(fmaf((g23.x - em) * er, eg, eb)), res.z);
            res.w = fmaf(ge, silu(fmaf((g23.y - em) * er, eg, eb)), res.w);
        }
    }
    ((float4*)out)[i4] = res;
}

// ---------------- launch ------------------------------------------------------
extern "C" void kernel_launch(void* const* d_in, const int* in_sizes, int n_in,
                              void* d_out, int out_size) {
    const float* x    = (const float*)d_in[0];
    const float* rw1  = (const float*)d_in[1];
    const float* rb1  = (const float*)d_in[2];
    const float* rw2  = (const float*)d_in[3];
    const float* rb2  = (const float*)d_in[4];
    const float* ew   = (const float*)d_in[5];
    const float* egam = (const float*)d_in[6];
    const float* ebet = (const float*)d_in[7];
    const float* sw   = (const float*)d_in[8];
    const float* sgam = (const float*)d_in[9];
    const float* sbet = (const float*)d_in[10];
    float* out = (float*)d_out;

    cudaFuncSetAttribute(gemm_kernel, cudaFuncAttributeMaxDynamicSharedMemorySize, SMEM_TOTAL);

    prep_kernel<<<1312, 256>>>(x, sw);
    router_kernel<<<1, 256>>>(rw1, rb1, rw2, rb2);
    vtrans_kernel<<<256, 256>>>();
    utrans_kernel<<<1024, 256>>>(ew);
    gemm_kernel<<<1152, 1024, SMEM_TOTAL>>>();
    finalize_kernel<<<4, 1024>>>();
    outtrans_kernel<<<256, 256>>>();
    combine_kernel<<<(BB * OO * HWSZ / 4) / 256, 256>>>(egam, ebet, sgam, sbet, out);
}

// round 16
// speedup vs baseline: 1.0205x; 1.0205x over previous
#include <cuda_runtime.h>
#include <cuda_fp16.h>
#include <math.h>

// Problem constants
#define BB   16
#define CC   256
#define OO   256
#define HH   32
#define WW   32
#define EE   4
#define CR   16
#define GG   8
#define CPG  32
#define HWSZ 1024
#define EPSV 1e-5f

#define PADW 34
#define PADPX (PADW * PADW)
#define NTILE 256                   // 16x16 winograd tiles per image
#define NSTG 4
#define TILE_A 16384                // 128 rows x 128B (K=64 fp16)
#define TILE_B 32768                // 256 rows x 128B
#define STAGE_BYTES (TILE_A + TILE_B)
#define SMEM_TOTAL (NSTG * STAGE_BYTES)   // 196608
#define YST 1026                    // padded Ybuf row stride (halves)
#define YBUF_BYTES (32 * YST * 2)   // 65664

// ---------------- scratch ----------------------------------------------------
__device__ float  g_pooled[BB * CC];
__device__ float  g_gate[BB * EE];
__device__ int    g_actlist[BB * EE];
__device__ int    g_nact;
__device__ __half g_xT[(size_t)BB * PADPX * CC];             // padded px-major fp16
__device__ __half g_swT[OO * CC];                            // shared 1x1 weights fp16
__device__ __half g_V[(size_t)BB * 16 * NTILE * CC];         // input winograd transform
__device__ __half g_U[(size_t)EE * 16 * OO * CC];            // weight winograd transform
__device__ __half g_M[(size_t)32 * 16 * 2 * 128 * 256];      // [apair][uv][thalf][tl][o]
__device__ __half g_shared_raw[(size_t)BB * OO * HWSZ];
__device__ __half g_expert_raw[(size_t)BB * EE * OO * HWSZ];
// GN partials for SHARED only: [b][group][warp_m 0..3][px_tile 0..7]
__device__ float  g_psum[BB * GG * 4 * 8];
__device__ float  g_psq [BB * GG * 4 * 8];
__device__ float  g_sh_mean[BB * GG], g_sh_rstd[BB * GG];
__device__ float  g_ex_mean[BB * EE * GG], g_ex_rstd[BB * EE * GG];

// ---------------- helpers ----------------------------------------------------
__device__ __forceinline__ float warpsum(float v) {
    #pragma unroll
    for (int o = 16; o > 0; o >>= 1) v += __shfl_down_sync(0xffffffffu, v, o);
    return v;
}
__device__ __forceinline__ float silu(float v) { return v / (1.0f + expf(-v)); }

__device__ __forceinline__ unsigned smem_u32(const void* p) {
    unsigned a;
    asm("{ .reg .u64 t; cvta.to.shared.u64 t, %1; cvt.u32.u64 %0, t; }" : "=r"(a) : "l"(p));
    return a;
}
__device__ __forceinline__ void cp16(unsigned dst, const void* src) {
    asm volatile("cp.async.cg.shared.global [%0], [%1], 16;" :: "r"(dst), "l"(src));
}
__device__ __forceinline__ void cp_commit() { asm volatile("cp.async.commit_group;"); }

__device__ __forceinline__ void ldm4(unsigned& r0, unsigned& r1, unsigned& r2, unsigned& r3,
                                     unsigned addr) {
    asm volatile("ldmatrix.sync.aligned.m8n8.x4.shared.b16 {%0,%1,%2,%3}, [%4];"
                 : "=r"(r0), "=r"(r1), "=r"(r2), "=r"(r3) : "r"(addr));
}

__device__ __forceinline__ void mma_f16(float* c, unsigned a0, unsigned a1, unsigned a2, unsigned a3,
                                        unsigned b0, unsigned b1) {
    asm volatile(
        "mma.sync.aligned.m16n8k16.row.col.f32.f16.f16.f32 "
        "{%0,%1,%2,%3}, {%4,%5,%6,%7}, {%8,%9}, {%0,%1,%2,%3};"
        : "+f"(c[0]), "+f"(c[1]), "+f"(c[2]), "+f"(c[3])
        : "r"(a0), "r"(a1), "r"(a2), "r"(a3), "r"(b0), "r"(b1));
}

// ---------------- K1: router (+ active list) -----------------------------------
__global__ void router_kernel(const float* __restrict__ w1, const float* __restrict__ b1,
                              const float* __restrict__ w2, const float* __restrict__ b2) {
    __shared__ float hs[BB][CR];
    __shared__ float lg[BB][EE];
    int tid = threadIdx.x;
    {
        int b = tid / CR, j = tid % CR;
        float s = b1[j];
        const float* wr = w1 + j * CC;
        const float* pr = g_pooled + b * CC;
        for (int c = 0; c < CC; c++) s = fmaf(wr[c], pr[c], s);
        hs[b][j] = silu(s);
    }
    __syncthreads();
    if (tid < BB * EE) {
        int b = tid / EE, e = tid % EE;
        float s = b2[e];
        for (int j = 0; j < CR; j++) s = fmaf(w2[e * CR + j], hs[b][j], s);
        lg[b][e] = s;
    }
    __syncthreads();
    if (tid < BB) {
        int b = tid;
        float m = lg[b][0];
        for (int e = 1; e < EE; e++) m = fmaxf(m, lg[b][e]);
        float p[EE]; float Z = 0.f;
        for (int e = 0; e < EE; e++) { p[e] = expf(lg[b][e] - m); Z += p[e]; }
        for (int e = 0; e < EE; e++) p[e] /= Z;
        int i1 = 0;
        for (int e = 1; e < EE; e++) if (p[e] > p[i1]) i1 = e;
        int i2 = -1;
        for (int e = 0; e < EE; e++) {
            if (e == i1) continue;
            if (i2 < 0 || p[e] > p[i2]) i2 = e;
        }
        float v1 = p[i1], v2 = p[i2], sum = v1 + v2;
        float wA = v1 / sum, wB = v2 / sum;
        if (wA < 0.01f) wA = 0.f;
        if (wB < 0.01f) wB = 0.f;
        for (int e = 0; e < EE; e++) g_gate[b * EE + e] = 0.f;
        g_gate[b * EE + i1] = wA;
        g_gate[b * EE + i2] = wB;
    }
    __syncthreads();
    if (tid == 0) {
        int n = 0;
        for (int be = 0; be < BB * EE; be++)
            if (g_gate[be] != 0.f) g_actlist[n++] = be;
        g_nact = n;
    }
}

// ---------------- K0: fused prep (xt + swt + pool + utrans) --------------------
// [0,544): x transpose; [544,800): shared w; [800,1312): pool; [1312,2336): utrans
__global__ void prep_kernel(const float* __restrict__ x, const float* __restrict__ sw,
                            const float* __restrict__ ew) {
    __shared__ float s[CC][33];
    __shared__ float s2[CC * 9];
    int bid = blockIdx.x;
    int tid = threadIdx.x;
    if (bid < 544) {
        int b = bid / 34;
        int hp = bid % 34;
        int h = hp - 1;
        __half* outrow = g_xT + ((size_t)b * PADPX + (size_t)hp * PADW) * CC;
        const __half hz = __float2half_rn(0.f);
        if (h < 0 || h >= HH) {
            for (int i = tid; i < PADW * CC; i += 256) outrow[i] = hz;
            return;
        }
        outrow[tid] = hz;
        outrow[33 * CC + tid] = hz;
        for (int i = tid; i < CC * WW; i += 256) {
            int c = i >> 5, w = i & 31;
            s[c][w] = x[((size_t)(b * CC + c)) * HWSZ + h * WW + w];
        }
        __syncthreads();
        for (int i = tid; i < WW * CC; i += 256) {
            int w = i >> 8, c = i & 255;
            outrow[(size_t)(w + 1) * CC + c] = __float2half_rn(s[c][w]);
        }
    } else if (bid < 800) {
        int idx = (bid - 544) * 256 + tid;
        int c = idx & 255, o = idx >> 8;
        g_swT[(o << 8) + c] = __float2half_rn(sw[idx]);
    } else if (bid < 1312) {
        int warp = tid >> 5, lane = tid & 31;
        int idx = (bid - 800) * 8 + warp;
        const float* p = x + (size_t)idx * HWSZ;
        float ps = 0.f;
        for (int i = lane; i < HWSZ; i += 32) ps += p[i];
        ps = warpsum(ps);
        if (lane == 0) g_pooled[idx] = ps * (1.0f / HWSZ);
    } else {
        int wb = bid - 1312;
        int e = wb >> 8, o = wb & 255;
        const float* src = ew + ((size_t)(e * OO + o)) * CC * 9;
        for (int i = tid; i < CC * 9; i += 256) s2[i] = src[i];
        __syncthreads();
        int c = tid;
        float g0[3], g1[3], g2[3];
        #pragma unroll
        for (int j = 0; j < 3; j++) {
            g0[j] = s2[c * 9 + 0 + j];
            g1[j] = s2[c * 9 + 3 + j];
            g2[j] = s2[c * 9 + 6 + j];
        }
        float zg[4][3];
        #pragma unroll
        for (int j = 0; j < 3; j++) {
            zg[0][j] = g0[j];
            zg[1][j] = 0.5f * (g0[j] + g1[j] + g2[j]);
            zg[2][j] = 0.5f * (g0[j] - g1[j] + g2[j]);
            zg[3][j] = g2[j];
        }
        __half* ub = g_U + ((size_t)e * 16) * OO * CC;
        #pragma unroll
        for (int i = 0; i < 4; i++) {
            float u0 = zg[i][0];
            float u1 = 0.5f * (zg[i][0] + zg[i][1] + zg[i][2]);
            float u2 = 0.5f * (zg[i][0] - zg[i][1] + zg[i][2]);
            float u3 = zg[i][2];
            ub[((size_t)(i * 4 + 0) * OO + o) * CC + c] = __float2half_rn(u0);
            ub[((size_t)(i * 4 + 1) * OO + o) * CC + c] = __float2half_rn(u1);
            ub[((size_t)(i * 4 + 2) * OO + o) * CC + c] = __float2half_rn(u2);
            ub[((size_t)(i * 4 + 3) * OO + o) * CC + c] = __float2half_rn(u3);
        }
    }
}

// ---------------- K2: input winograd transform V = B^T d B ---------------------
__global__ void vtrans_kernel() {
    int bid = blockIdx.x;
    int b = bid >> 4, th = bid & 15;
    int c = threadIdx.x;
    const __half* xb = g_xT + ((size_t)b * PADPX) * CC + c;
    __half* vb = g_V + ((size_t)b * 16) * NTILE * CC;
    for (int tw = 0; tw < 16; tw++) {
        float d[4][4];
        #pragma unroll
        for (int i = 0; i < 4; i++)
            #pragma unroll
            for (int j = 0; j < 4; j++)
                d[i][j] = __half2float(xb[((size_t)(2 * th + i) * PADW + 2 * tw + j) * CC]);
        float z[4][4];
        #pragma unroll
        for (int j = 0; j < 4; j++) {
            z[0][j] = d[0][j] - d[2][j];
            z[1][j] = d[1][j] + d[2][j];
            z[2][j] = d[2][j] - d[1][j];
            z[3][j] = d[1][j] - d[3][j];
        }
        int t = th * 16 + tw;
        #pragma unroll
        for (int i = 0; i < 4; i++) {
            float v0 = z[i][0] - z[i][2];
            float v1 = z[i][1] + z[i][2];
            float v2 = z[i][2] - z[i][1];
            float v3 = z[i][1] - z[i][3];
            vb[((size_t)(i * 4 + 0) * NTILE + t) * CC + c] = __float2half_rn(v0);
            vb[((size_t)(i * 4 + 1) * NTILE + t) * CC + c] = __float2half_rn(v1);
            vb[((size_t)(i * 4 + 2) * NTILE + t) * CC + c] = __float2half_rn(v2);
            vb[((size_t)(i * 4 + 3) * NTILE + t) * CC + c] = __float2half_rn(v3);
        }
    }
}

// ---------------- K3: fp16 warp-MMA GEMM --------------------------------------
// grid 384: id<256 expert (apair,thalf,uvquad; NITER=16, fragment-direct M stores)
//           id>=256 shared conv (NITER=4, transpose epilogue + GN partials)
__global__ void __launch_bounds__(1024, 1)
gemm_kernel() {
    extern __shared__ char smem[];
    unsigned sb = smem_u32(smem);
    int tid = threadIdx.x, warp = tid >> 5, lane = tid & 31;
    int warp_m = warp >> 3, warp_n = warp & 7;
    int g = lane >> 2, q = lane & 3;

    int id = blockIdx.x;
    bool is_shared = (id >= 256);
    const __half *aSrcBase, *bSrcBase;
    int NITER, apair = 0, thalf = 0, uvq = 0, slot_b = 0, pxtile = 0;
    __half* sh_out = 0;
    int sh_p0 = 0;

    int arow = tid >> 3, aq = tid & 7;
    int brow = tid >> 2, bh = tid & 3;

    if (is_shared) {
        int sid = id - 256;
        int b = sid >> 3;
        pxtile = sid & 7;
        sh_p0 = pxtile * 128;
        int p = sh_p0 + arow;
        int ppad = ((p >> 5) + 1) * PADW + (p & 31) + 1;
        aSrcBase = g_xT + ((size_t)b * PADPX + ppad) * CC + aq * 8;
        bSrcBase = g_swT + ((size_t)brow << 8) + bh * 16;
        sh_out = g_shared_raw + (size_t)b * OO * HWSZ;
        slot_b = b;
        NITER = 4;
    } else {
        apair = id >> 3;
        if (apair >= g_nact) return;
        thalf = (id >> 2) & 1;
        uvq = id & 3;
        int be = g_actlist[apair];
        int b = be >> 2, e = be & 3;
        aSrcBase = g_V + (((size_t)b * 16) * NTILE + thalf * 128 + arow) * CC + aq * 8;
        bSrcBase = g_U + (((size_t)e * 16) * OO + brow) * CC + bh * 16;
        NITER = 16;
    }

    unsigned xrA = (unsigned)(arow & 7) << 4;
    unsigned xrB = (unsigned)(brow & 7) << 4;
    unsigned aDstRow = sb + arow * 128;
    unsigned bDstRow = sb + TILE_A + brow * 128;
    unsigned aq16 = (unsigned)aq * 16, bh32 = (unsigned)bh * 32;

    auto load_stage = [&](int iter, int buf) {
        long long aoff, boff;
        if (is_shared) { aoff = boff = iter << 6; }
        else {
            int uv = uvq * 4 + (iter >> 2);
            int c0 = (iter & 3) << 6;
            aoff = (long long)uv * NTILE * CC + c0;
            boff = (long long)uv * OO * CC + c0;
        }
        const __half* as = aSrcBase + aoff;
        const __half* bs = bSrcBase + boff;
        unsigned aDst = aDstRow + buf * STAGE_BYTES;
        unsigned bDst = bDstRow + buf * STAGE_BYTES;
        cp16(aDst + (aq16 ^ xrA), as);
        cp16(bDst + ((bh32)      ^ xrB), bs);
        cp16(bDst + ((bh32 + 16) ^ xrB), bs + 8);
        cp_commit();
    };

    unsigned l7 = lane & 7;
    unsigned key = l7 << 4;
    unsigned rsel = (((unsigned)lane >> 3) & 1u) * 8u;
    unsigned hsel = ((unsigned)lane >> 4) << 4;
    unsigned aOff = ((unsigned)(warp_m * 32) + l7 + rsel) * 128u;
    unsigned bOff = TILE_A + ((unsigned)(warp_n * 32) + l7 + rsel) * 128u;
    unsigned kphase = (unsigned)warp & 3u;

    float acc[2][4][4] = {};

    auto compute = [&](int buf) {
        unsigned base = sb + buf * STAGE_BYTES;
        #pragma unroll
        for (int ks0 = 0; ks0 < 4; ks0++) {
            unsigned kstep = ((unsigned)ks0 + kphase) & 3u;
            unsigned kb = ((kstep * 32u) + hsel) ^ key;
            unsigned a[2][4];
            #pragma unroll
            for (int mi = 0; mi < 2; mi++)
                ldm4(a[mi][0], a[mi][1], a[mi][2], a[mi][3],
                     base + aOff + mi * 2048u + kb);
            unsigned bf[2][4];
            #pragma unroll
            for (int j = 0; j < 2; j++)
                ldm4(bf[j][0], bf[j][1], bf[j][2], bf[j][3],
                     base + bOff + j * 2048u + kb);
            #pragma unroll
            for (int mi = 0; mi < 2; mi++) {
                #pragma unroll
                for (int j = 0; j < 2; j++) {
                    mma_f16(acc[mi][2 * j],     a[mi][0], a[mi][1], a[mi][2], a[mi][3],
                            bf[j][0], bf[j][2]);
                    mma_f16(acc[mi][2 * j + 1], a[mi][0], a[mi][1], a[mi][2], a[mi][3],
                            bf[j][1], bf[j][3]);
                }
            }
        }
    };

    // direct fragment store of one uv group to g_M, then reset accumulators
    auto store_uv = [&](int gi) {
        __half* Mu = g_M + ((((size_t)apair * 16 + uvq * 4 + gi) * 2 + thalf) * 128) * 256;
        #pragma unroll
        for (int mi = 0; mi < 2; mi++) {
            int m0 = warp_m * 32 + mi * 16 + g;
            #pragma unroll
            for (int ni = 0; ni < 4; ni++) {
                int n = warp_n * 32 + ni * 8 + 2 * q;
                *(__half2*)(Mu + (size_t)m0 * 256 + n) =
                    __floats2half2_rn(acc[mi][ni][0], acc[mi][ni][1]);
                *(__half2*)(Mu + (size_t)(m0 + 8) * 256 + n) =
                    __floats2half2_rn(acc[mi][ni][2], acc[mi][ni][3]);
                acc[mi][ni][0] = acc[mi][ni][1] = acc[mi][ni][2] = acc[mi][ni][3] = 0.f;
            }
        }
    };

    // pipeline: barrier per 2 iters; expert drains M per uv (no smem involved)
    load_stage(0, 0);
    load_stage(1, 1);
    for (int i = 0; i < NITER; i += 2) {
        asm volatile("cp.async.wait_group 0;" ::: "memory");
        __syncthreads();
        if (i + 2 < NITER) load_stage(i + 2, (i + 2) & 3);
        if (i + 3 < NITER) load_stage(i + 3, (i + 3) & 3);
        compute(i & 3);
        compute((i + 1) & 3);
        if (!is_shared && (i & 3) == 2) store_uv(i >> 2);
    }
    if (!is_shared) return;

    // ---- shared path: GN partials + transpose epilogue (all compute done) ----
    {
        float s = 0.f, sq = 0.f;
        #pragma unroll
        for (int mi = 0; mi < 2; mi++)
            #pragma unroll
            for (int ni = 0; ni < 4; ni++)
                #pragma unroll
                for (int c = 0; c < 4; c++) {
                    float v = acc[mi][ni][c];
                    s += v;
                    sq = fmaf(v, v, sq);
                }
        s = warpsum(s); sq = warpsum(sq);
        if (lane == 0) {
            int idx = ((slot_b * GG + warp_n) * 4 + warp_m) * 8 + pxtile;
            g_psum[idx] = s;
            g_psq[idx]  = sq;
        }
    }
    __syncthreads();

    float* T = (float*)smem;
    #pragma unroll
    for (int mi = 0; mi < 2; mi++) {
        int m = warp_m * 32 + mi * 16 + g;
        #pragma unroll
        for (int ni = 0; ni < 4; ni++) {
            int n = warp_n * 32 + ni * 8 + 2 * q;
            T[n * 132 + m]           = acc[mi][ni][0];
            T[(n + 1) * 132 + m]     = acc[mi][ni][1];
            T[n * 132 + m + 8]       = acc[mi][ni][2];
            T[(n + 1) * 132 + m + 8] = acc[mi][ni][3];
        }
    }
    __syncthreads();

    #pragma unroll
    for (int rr = 0; rr < 8; rr++) {
        int n = warp * 8 + rr;
        float4 v = *(const float4*)(T + n * 132 + lane * 4);
        __half2 h01 = __floats2half2_rn(v.x, v.y);
        __half2 h23 = __floats2half2_rn(v.z, v.w);
        uint2 u;
        u.x = *(unsigned*)&h01;
        u.y = *(unsigned*)&h23;
        *(uint2*)(sh_out + (size_t)n * HWSZ + sh_p0 + lane * 4) = u;
    }
}

// ---------------- K4: output transform + expert GN stats + shared finalize -----
// blocks [0,256): outtrans (apair*8+grp); [256,272): shared GN finalize
__global__ void outfin_kernel() {
    extern __shared__ __half Ybuf[];          // [32][YST]
    __shared__ float ss[8], sqs[8];
    int bid = blockIdx.x;
    int tid = threadIdx.x, w = tid >> 5, lane = tid & 31;

    if (bid >= 256) {
        int item = (bid - 256) * 8 + w;        // 0..127
        if (item >= BB * GG) return;
        int slot = item / GG, g = item % GG;
        int base = (slot * GG + g) * 32;
        float S = warpsum(g_psum[base + lane]);
        float Q = warpsum(g_psq[base + lane]);
        if (lane == 0) {
            const float inv = 1.0f / (CPG * HWSZ);
            float mean = S * inv;
            float var = Q * inv - mean * mean;
            g_sh_mean[slot * GG + g] = mean;
            g_sh_rstd[slot * GG + g] = rsqrtf(var + EPSV);
        }
        return;
    }

    int apair = bid >> 3, grp = bid & 7;
    if (apair >= g_nact) return;
    int be = g_actlist[apair];

    int opl = lane & 15, tsub = lane >> 4;
    int o_loc = 2 * opl;
    int o = grp * CPG + o_loc;
    const __half* Mb = g_M + (size_t)apair * 16 * 2 * 128 * 256;

    float s = 0.f, sq = 0.f;
    for (int tt = 0; tt < 16; tt++) {
        int t = w * 32 + tsub * 16 + tt;
        int tl = t & 127, th2 = t >> 7;
        float2 Mv[16];
        #pragma unroll
        for (int uv = 0; uv < 16; uv++) {
            __half2 h = *(const __half2*)(Mb + (((size_t)uv * 2 + th2) * 128 + tl) * 256 + o);
            Mv[uv] = __half22float2(h);
        }
        float zm0x[4], zm1x[4], zm0y[4], zm1y[4];
        #pragma unroll
        for (int j = 0; j < 4; j++) {
            zm0x[j] = Mv[j].x + Mv[4 + j].x + Mv[8 + j].x;
            zm1x[j] = Mv[4 + j].x - Mv[8 + j].x - Mv[12 + j].x;
            zm0y[j] = Mv[j].y + Mv[4 + j].y + Mv[8 + j].y;
            zm1y[j] = Mv[4 + j].y - Mv[8 + j].y - Mv[12 + j].y;
        }
        float y00x = zm0x[0] + zm0x[1] + zm0x[2];
        float y01x = zm0x[1] - zm0x[2] - zm0x[3];
        float y10x = zm1x[0] + zm1x[1] + zm1x[2];
        float y11x = zm1x[1] - zm1x[2] - zm1x[3];
        float y00y = zm0y[0] + zm0y[1] + zm0y[2];
        float y01y = zm0y[1] - zm0y[2] - zm0y[3];
        float y10y = zm1y[0] + zm1y[1] + zm1y[2];
        float y11y = zm1y[1] - zm1y[2] - zm1y[3];

        s += y00x + y01x + y10x + y11x + y00y + y01y + y10y + y11y;
        sq = fmaf(y00x, y00x, sq); sq = fmaf(y01x, y01x, sq);
        sq = fmaf(y10x, y10x, sq); sq = fmaf(y11x, y11x, sq);
        sq = fmaf(y00y, y00y, sq); sq = fmaf(y01y, y01y, sq);
        sq = fmaf(y10y, y10y, sq); sq = fmaf(y11y, y11y, sq);

        int th = t >> 4, tw = t & 15;
        int px = th * 64 + 2 * tw;
        *(__half2*)&Ybuf[o_loc * YST + px]            = __floats2half2_rn(y00x, y01x);
        *(__half2*)&Ybuf[o_loc * YST + px + 32]       = __floats2half2_rn(y10x, y11x);
        *(__half2*)&Ybuf[(o_loc + 1) * YST + px]      = __floats2half2_rn(y00y, y01y);
        *(__half2*)&Ybuf[(o_loc + 1) * YST + px + 32] = __floats2half2_rn(y10y, y11y);
    }
    s = warpsum(s); sq = warpsum(sq);
    if (lane == 0) { ss[w] = s; sqs[w] = sq; }
    __syncthreads();
    if (tid == 0) {
        float S = 0.f, Q = 0.f;
        #pragma unroll
        for (int i = 0; i < 8; i++) { S += ss[i]; Q += sqs[i]; }
        const float inv = 1.0f / (CPG * HWSZ);
        float mean = S * inv;
        float var = Q * inv - mean * mean;
        g_ex_mean[be * GG + grp] = mean;
        g_ex_rstd[be * GG + grp] = rsqrtf(var + EPSV);
    }
    // coalesced copy-out Ybuf -> expert_raw
    __half* outb = g_expert_raw + ((size_t)be * OO + grp * CPG) * HWSZ;
    for (int idx = tid; idx < 32 * 512; idx += 256) {
        int row = idx >> 9, c = idx & 511;
        unsigned v = *(unsigned*)&Ybuf[row * YST + c * 2];
        ((unsigned*)(outb + (size_t)row * HWSZ))[c] = v;
    }
}

// ---------------- K5: normalize + SiLU + gated combine (half4 loads) -----------
__global__ void combine_kernel(const float* __restrict__ egam, const float* __restrict__ ebet,
                               const float* __restrict__ sgam, const float* __restrict__ sbet,
                               float* __restrict__ out) {
    size_t i4 = (size_t)blockIdx.x * 256 + threadIdx.x;
    size_t t = i4 >> 8;
    int o = (int)(t & 255);
    int b = (int)(t >> 8);
    int g = o >> 5;

    uint2 vv = ((const uint2*)g_shared_raw)[i4];
    __half2 v01 = *(__half2*)&vv.x, v23 = *(__half2*)&vv.y;
    float2 f01 = __half22float2(v01), f23 = __half22float2(v23);
    float m = g_sh_mean[b * GG + g], r = g_sh_rstd[b * GG + g];
    float ga = sgam[o], be_ = sbet[o];
    float4 res;
    res.x = silu(fmaf((f01.x - m) * r, ga, be_));
    res.y = silu(fmaf((f01.y - m) * r, ga, be_));
    res.z = silu(fmaf((f23.x - m) * r, ga, be_));
    res.w = silu(fmaf((f23.y - m) * r, ga, be_));

    #pragma unroll
    for (int e = 0; e < EE; e++) {
        float ge = g_gate[b * EE + e];
        if (ge != 0.f) {
            int beg = b * EE + e;
            size_t ei = ((size_t)beg * OO + o) * (HWSZ / 4) + (i4 & 255);
            uint2 ew2 = ((const uint2*)g_expert_raw)[ei];
            __half2 e01 = *(__half2*)&ew2.x, e23 = *(__half2*)&ew2.y;
            float2 g01 = __half22float2(e01), g23 = __half22float2(e23);
            float em = g_ex_mean[beg * GG + g], er = g_ex_rstd[beg * GG + g];
            float eg = egam[e * OO + o], eb = ebet[e * OO + o];
            res.x = fmaf(ge, silu(fmaf((g01.x - em) * er, eg, eb)), res.x);
            res.y = fmaf(ge, silu(fmaf((g01.y - em) * er, eg, eb)), res.y);
            res.z = fmaf(ge, silu(fmaf((g23.x - em) * er, eg, eb)), res.z);
            res.w = fmaf(ge, silu(fmaf((g23.y - em) * er, eg, eb)), res.w);
        }
    }
    ((float4*)out)[i4] = res;
}

// ---------------- launch ------------------------------------------------------
extern "C" void kernel_launch(void* const* d_in, const int* in_sizes, int n_in,
                              void* d_out, int out_size) {
    const float* x    = (const float*)d_in[0];
    const float* rw1  = (const float*)d_in[1];
    const float* rb1  = (const float*)d_in[2];
    const float* rw2  = (const float*)d_in[3];
    const float* rb2  = (const float*)d_in[4];
    const float* ew   = (const float*)d_in[5];
    const float* egam = (const float*)d_in[6];
    const float* ebet = (const float*)d_in[7];
    const float* sw   = (const float*)d_in[8];
    const float* sgam = (const float*)d_in[9];
    const float* sbet = (const float*)d_in[10];
    float* out = (float*)d_out;

    cudaFuncSetAttribute(gemm_kernel, cudaFuncAttributeMaxDynamicSharedMemorySize, SMEM_TOTAL);
    cudaFuncSetAttribute(outfin_kernel, cudaFuncAttributeMaxDynamicSharedMemorySize, YBUF_BYTES);

    prep_kernel<<<2336, 256>>>(x, sw, ew);
    router_kernel<<<1, 256>>>(rw1, rb1, rw2, rb2);
    vtrans_kernel<<<256, 256>>>();
    gemm_kernel<<<384, 1024, SMEM_TOTAL>>>();
    outfin_kernel<<<272, 256, YBUF_BYTES>>>();
    combine_kernel<<<(BB * OO * HWSZ / 4) / 256, 256>>>(egam, ebet, sgam, sbet, out);
}

// round 17
// speedup vs baseline: 1.0327x; 1.0120x over previous
#include <cuda_runtime.h>
#include <cuda_fp16.h>
#include <math.h>

// Problem constants
#define BB   16
#define CC   256
#define OO   256
#define HH   32
#define WW   32
#define EE   4
#define CR   16
#define GG   8
#define CPG  32
#define HWSZ 1024
#define EPSV 1e-5f

#define PADW 34
#define PADPX (PADW * PADW)
#define NTILE 256                   // 16x16 winograd tiles per image
#define NSTG 4
#define TILE_A 16384                // 128 rows x 128B (K=64 fp16)
#define TILE_B 32768                // 256 rows x 128B
#define STAGE_BYTES (TILE_A + TILE_B)
#define SMEM_TOTAL (NSTG * STAGE_BYTES)   // 196608
#define YST 1026                    // padded Ybuf row stride (halves)
#define YBUF_BYTES (32 * YST * 2)   // 65664

// ---------------- scratch ----------------------------------------------------
__device__ float  g_poolp[BB * 32 * CC];                     // per-row pool partials
__device__ float  g_pooled[BB * CC];
__device__ float  g_gate[BB * EE];
__device__ int    g_actlist[BB * EE];
__device__ int    g_nact;
__device__ __half g_xT[(size_t)BB * PADPX * CC];             // padded px-major fp16
__device__ __half g_swT[OO * CC];                            // shared 1x1 weights fp16
__device__ __half g_V[(size_t)BB * 16 * NTILE * CC];         // input winograd transform
__device__ __half g_U[(size_t)EE * 16 * OO * CC];            // weight winograd transform
__device__ __half g_M[(size_t)32 * 16 * 2 * 128 * 256];      // [apair][uv][thalf][tl][o]
__device__ __half g_shared_raw[(size_t)BB * OO * HWSZ];
__device__ __half g_expert_raw[(size_t)BB * EE * OO * HWSZ];
// GN partials for SHARED only: [b][group][warp_m 0..3][px_tile 0..7]
__device__ float  g_psum[BB * GG * 4 * 8];
__device__ float  g_psq [BB * GG * 4 * 8];
__device__ float  g_sh_mean[BB * GG], g_sh_rstd[BB * GG];
__device__ float  g_ex_mean[BB * EE * GG], g_ex_rstd[BB * EE * GG];

// ---------------- helpers ----------------------------------------------------
__device__ __forceinline__ float warpsum(float v) {
    #pragma unroll
    for (int o = 16; o > 0; o >>= 1) v += __shfl_down_sync(0xffffffffu, v, o);
    return v;
}
__device__ __forceinline__ float silu(float v) { return v / (1.0f + expf(-v)); }

__device__ __forceinline__ unsigned smem_u32(const void* p) {
    unsigned a;
    asm("{ .reg .u64 t; cvta.to.shared.u64 t, %1; cvt.u32.u64 %0, t; }" : "=r"(a) : "l"(p));
    return a;
}
__device__ __forceinline__ void cp16(unsigned dst, const void* src) {
    asm volatile("cp.async.cg.shared.global [%0], [%1], 16;" :: "r"(dst), "l"(src));
}
__device__ __forceinline__ void cp_commit() { asm volatile("cp.async.commit_group;"); }

__device__ __forceinline__ void ldm4(unsigned& r0, unsigned& r1, unsigned& r2, unsigned& r3,
                                     unsigned addr) {
    asm volatile("ldmatrix.sync.aligned.m8n8.x4.shared.b16 {%0,%1,%2,%3}, [%4];"
                 : "=r"(r0), "=r"(r1), "=r"(r2), "=r"(r3) : "r"(addr));
}

__device__ __forceinline__ void mma_f16(float* c, unsigned a0, unsigned a1, unsigned a2, unsigned a3,
                                        unsigned b0, unsigned b1) {
    asm volatile(
        "mma.sync.aligned.m16n8k16.row.col.f32.f16.f16.f32 "
        "{%0,%1,%2,%3}, {%4,%5,%6,%7}, {%8,%9}, {%0,%1,%2,%3};"
        : "+f"(c[0]), "+f"(c[1]), "+f"(c[2]), "+f"(c[3])
        : "r"(a0), "r"(a1), "r"(a2), "r"(a3), "r"(b0), "r"(b1));
}

// ---------------- K1: router (+ active list) -----------------------------------
__global__ void router_kernel(const float* __restrict__ w1, const float* __restrict__ b1,
                              const float* __restrict__ w2, const float* __restrict__ b2) {
    __shared__ float hs[BB][CR];
    __shared__ float lg[BB][EE];
    int tid = threadIdx.x;
    {
        int b = tid / CR, j = tid % CR;
        float s = b1[j];
        const float* wr = w1 + j * CC;
        const float* pr = g_pooled + b * CC;
        for (int c = 0; c < CC; c++) s = fmaf(wr[c], pr[c], s);
        hs[b][j] = silu(s);
    }
    __syncthreads();
    if (tid < BB * EE) {
        int b = tid / EE, e = tid % EE;
        float s = b2[e];
        for (int j = 0; j < CR; j++) s = fmaf(w2[e * CR + j], hs[b][j], s);
        lg[b][e] = s;
    }
    __syncthreads();
    if (tid < BB) {
        int b = tid;
        float m = lg[b][0];
        for (int e = 1; e < EE; e++) m = fmaxf(m, lg[b][e]);
        float p[EE]; float Z = 0.f;
        for (int e = 0; e < EE; e++) { p[e] = expf(lg[b][e] - m); Z += p[e]; }
        for (int e = 0; e < EE; e++) p[e] /= Z;
        int i1 = 0;
        for (int e = 1; e < EE; e++) if (p[e] > p[i1]) i1 = e;
        int i2 = -1;
        for (int e = 0; e < EE; e++) {
            if (e == i1) continue;
            if (i2 < 0 || p[e] > p[i2]) i2 = e;
        }
        float v1 = p[i1], v2 = p[i2], sum = v1 + v2;
        float wA = v1 / sum, wB = v2 / sum;
        if (wA < 0.01f) wA = 0.f;
        if (wB < 0.01f) wB = 0.f;
        for (int e = 0; e < EE; e++) g_gate[b * EE + e] = 0.f;
        g_gate[b * EE + i1] = wA;
        g_gate[b * EE + i2] = wB;
    }
    __syncthreads();
    if (tid == 0) {
        int n = 0;
        for (int be = 0; be < BB * EE; be++)
            if (g_gate[be] != 0.f) g_actlist[n++] = be;
        g_nact = n;
    }
}

// ---------------- K0: fused prep (xt+poolpartial + swt + utrans) ---------------
// [0,544): x transpose + row pool partials; [544,800): shared w; [800,1824): utrans
__global__ void prep_kernel(const float* __restrict__ x, const float* __restrict__ sw,
                            const float* __restrict__ ew) {
    __shared__ float s[CC][33];
    __shared__ float s2[CC * 9];
    int bid = blockIdx.x;
    int tid = threadIdx.x;
    if (bid < 544) {
        int b = bid / 34;
        int hp = bid % 34;
        int h = hp - 1;
        __half* outrow = g_xT + ((size_t)b * PADPX + (size_t)hp * PADW) * CC;
        const __half hz = __float2half_rn(0.f);
        if (h < 0 || h >= HH) {
            for (int i = tid; i < PADW * CC; i += 256) outrow[i] = hz;
            return;
        }
        outrow[tid] = hz;
        outrow[33 * CC + tid] = hz;
        for (int i = tid; i < CC * WW; i += 256) {
            int c = i >> 5, w = i & 31;
            s[c][w] = x[((size_t)(b * CC + c)) * HWSZ + h * WW + w];
        }
        __syncthreads();
        for (int i = tid; i < WW * CC; i += 256) {
            int w = i >> 8, c = i & 255;
            outrow[(size_t)(w + 1) * CC + c] = __float2half_rn(s[c][w]);
        }
        // row pool partial: thread = channel
        float ps = 0.f;
        #pragma unroll
        for (int w = 0; w < 32; w++) ps += s[tid][w];
        g_poolp[((size_t)b * 32 + h) * CC + tid] = ps;
    } else if (bid < 800) {
        int idx = (bid - 544) * 256 + tid;
        int c = idx & 255, o = idx >> 8;
        g_swT[(o << 8) + c] = __float2half_rn(sw[idx]);
    } else {
        int wb = bid - 800;
        int e = wb >> 8, o = wb & 255;
        const float* src = ew + ((size_t)(e * OO + o)) * CC * 9;
        for (int i = tid; i < CC * 9; i += 256) s2[i] = src[i];
        __syncthreads();
        int c = tid;
        float g0[3], g1[3], g2[3];
        #pragma unroll
        for (int j = 0; j < 3; j++) {
            g0[j] = s2[c * 9 + 0 + j];
            g1[j] = s2[c * 9 + 3 + j];
            g2[j] = s2[c * 9 + 6 + j];
        }
        float zg[4][3];
        #pragma unroll
        for (int j = 0; j < 3; j++) {
            zg[0][j] = g0[j];
            zg[1][j] = 0.5f * (g0[j] + g1[j] + g2[j]);
            zg[2][j] = 0.5f * (g0[j] - g1[j] + g2[j]);
            zg[3][j] = g2[j];
        }
        __half* ub = g_U + ((size_t)e * 16) * OO * CC;
        #pragma unroll
        for (int i = 0; i < 4; i++) {
            float u0 = zg[i][0];
            float u1 = 0.5f * (zg[i][0] + zg[i][1] + zg[i][2]);
            float u2 = 0.5f * (zg[i][0] - zg[i][1] + zg[i][2]);
            float u3 = zg[i][2];
            ub[((size_t)(i * 4 + 0) * OO + o) * CC + c] = __float2half_rn(u0);
            ub[((size_t)(i * 4 + 1) * OO + o) * CC + c] = __float2half_rn(u1);
            ub[((size_t)(i * 4 + 2) * OO + o) * CC + c] = __float2half_rn(u2);
            ub[((size_t)(i * 4 + 3) * OO + o) * CC + c] = __float2half_rn(u3);
        }
    }
}

// ---------------- K2: input winograd transform (half2, rolling cols) + poolred -
// blocks [0,256): vtrans (b*16+th), 256 thr = 2 tw-halves x 128 channel-pairs
// blocks [256,272): pool reduce over h
__global__ void vtrans_kernel() {
    int bid = blockIdx.x;
    int tid = threadIdx.x;
    if (bid >= 256) {
        int b = bid - 256;
        float ssum = 0.f;
        for (int h = 0; h < 32; h++) ssum += g_poolp[((size_t)b * 32 + h) * CC + tid];
        g_pooled[b * CC + tid] = ssum * (1.0f / HWSZ);
        return;
    }
    int b = bid >> 4, th = bid & 15;
    int half = tid >> 7;             // tw range: 0..7 or 8..15
    int c2 = tid & 127;              // channel pair
    const __half2* xb2 = (const __half2*)(g_xT + (size_t)b * PADPX * CC);
    __half2* vb2 = (__half2*)(g_V + (size_t)b * 16 * NTILE * CC);

    int tw0 = half * 8;
    float2 cb[4][4];
    #pragma unroll
    for (int i = 0; i < 4; i++) {
        cb[i][2] = __half22float2(xb2[(size_t)((2 * th + i) * PADW + 2 * tw0)     * 128 + c2]);
        cb[i][3] = __half22float2(xb2[(size_t)((2 * th + i) * PADW + 2 * tw0 + 1) * 128 + c2]);
    }
    for (int twl = 0; twl < 8; twl++) {
        int tw = tw0 + twl;
        #pragma unroll
        for (int i = 0; i < 4; i++) {
            cb[i][0] = cb[i][2]; cb[i][1] = cb[i][3];
            cb[i][2] = __half22float2(xb2[(size_t)((2 * th + i) * PADW + 2 * tw + 2) * 128 + c2]);
            cb[i][3] = __half22float2(xb2[(size_t)((2 * th + i) * PADW + 2 * tw + 3) * 128 + c2]);
        }
        float2 z[4][4];
        #pragma unroll
        for (int j = 0; j < 4; j++) {
            z[0][j].x = cb[0][j].x - cb[2][j].x; z[0][j].y = cb[0][j].y - cb[2][j].y;
            z[1][j].x = cb[1][j].x + cb[2][j].x; z[1][j].y = cb[1][j].y + cb[2][j].y;
            z[2][j].x = cb[2][j].x - cb[1][j].x; z[2][j].y = cb[2][j].y - cb[1][j].y;
            z[3][j].x = cb[1][j].x - cb[3][j].x; z[3][j].y = cb[1][j].y - cb[3][j].y;
        }
        int t = th * 16 + tw;
        #pragma unroll
        for (int i = 0; i < 4; i++) {
            float2 v0, v1, v2, v3;
            v0.x = z[i][0].x - z[i][2].x; v0.y = z[i][0].y - z[i][2].y;
            v1.x = z[i][1].x + z[i][2].x; v1.y = z[i][1].y + z[i][2].y;
            v2.x = z[i][2].x - z[i][1].x; v2.y = z[i][2].y - z[i][1].y;
            v3.x = z[i][1].x - z[i][3].x; v3.y = z[i][1].y - z[i][3].y;
            vb2[(size_t)((i * 4 + 0) * NTILE + t) * 128 + c2] = __floats2half2_rn(v0.x, v0.y);
            vb2[(size_t)((i * 4 + 1) * NTILE + t) * 128 + c2] = __floats2half2_rn(v1.x, v1.y);
            vb2[(size_t)((i * 4 + 2) * NTILE + t) * 128 + c2] = __floats2half2_rn(v2.x, v2.y);
            vb2[(size_t)((i * 4 + 3) * NTILE + t) * 128 + c2] = __floats2half2_rn(v3.x, v3.y);
        }
    }
}

// ---------------- K3: fp16 warp-MMA GEMM --------------------------------------
// grid 384: id<256 expert (apair,thalf,uvquad; NITER=16, fragment-direct M stores)
//           id>=256 shared conv (NITER=4, transpose epilogue + GN partials)
__global__ void __launch_bounds__(1024, 1)
gemm_kernel() {
    extern __shared__ char smem[];
    unsigned sb = smem_u32(smem);
    int tid = threadIdx.x, warp = tid >> 5, lane = tid & 31;
    int warp_m = warp >> 3, warp_n = warp & 7;
    int g = lane >> 2, q = lane & 3;

    int id = blockIdx.x;
    bool is_shared = (id >= 256);
    const __half *aSrcBase, *bSrcBase;
    int NITER, apair = 0, thalf = 0, uvq = 0, slot_b = 0, pxtile = 0;
    __half* sh_out = 0;
    int sh_p0 = 0;

    int arow = tid >> 3, aq = tid & 7;
    int brow = tid >> 2, bh = tid & 3;

    if (is_shared) {
        int sid = id - 256;
        int b = sid >> 3;
        pxtile = sid & 7;
        sh_p0 = pxtile * 128;
        int p = sh_p0 + arow;
        int ppad = ((p >> 5) + 1) * PADW + (p & 31) + 1;
        aSrcBase = g_xT + ((size_t)b * PADPX + ppad) * CC + aq * 8;
        bSrcBase = g_swT + ((size_t)brow << 8) + bh * 16;
        sh_out = g_shared_raw + (size_t)b * OO * HWSZ;
        slot_b = b;
        NITER = 4;
    } else {
        apair = id >> 3;
        if (apair >= g_nact) return;
        thalf = (id >> 2) & 1;
        uvq = id & 3;
        int be = g_actlist[apair];
        int b = be >> 2, e = be & 3;
        aSrcBase = g_V + (((size_t)b * 16) * NTILE + thalf * 128 + arow) * CC + aq * 8;
        bSrcBase = g_U + (((size_t)e * 16) * OO + brow) * CC + bh * 16;
        NITER = 16;
    }

    unsigned xrA = (unsigned)(arow & 7) << 4;
    unsigned xrB = (unsigned)(brow & 7) << 4;
    unsigned aDstRow = sb + arow * 128;
    unsigned bDstRow = sb + TILE_A + brow * 128;
    unsigned aq16 = (unsigned)aq * 16, bh32 = (unsigned)bh * 32;

    auto load_stage = [&](int iter, int buf) {
        long long aoff, boff;
        if (is_shared) { aoff = boff = iter << 6; }
        else {
            int uv = uvq * 4 + (iter >> 2);
            int c0 = (iter & 3) << 6;
            aoff = (long long)uv * NTILE * CC + c0;
            boff = (long long)uv * OO * CC + c0;
        }
        const __half* as = aSrcBase + aoff;
        const __half* bs = bSrcBase + boff;
        unsigned aDst = aDstRow + buf * STAGE_BYTES;
        unsigned bDst = bDstRow + buf * STAGE_BYTES;
        cp16(aDst + (aq16 ^ xrA), as);
        cp16(bDst + ((bh32)      ^ xrB), bs);
        cp16(bDst + ((bh32 + 16) ^ xrB), bs + 8);
        cp_commit();
    };

    unsigned l7 = lane & 7;
    unsigned key = l7 << 4;
    unsigned rsel = (((unsigned)lane >> 3) & 1u) * 8u;
    unsigned hsel = ((unsigned)lane >> 4) << 4;
    unsigned aOff = ((unsigned)(warp_m * 32) + l7 + rsel) * 128u;
    unsigned bOff = TILE_A + ((unsigned)(warp_n * 32) + l7 + rsel) * 128u;
    unsigned kphase = (unsigned)warp & 3u;

    float acc[2][4][4] = {};

    auto compute = [&](int buf) {
        unsigned base = sb + buf * STAGE_BYTES;
        #pragma unroll
        for (int ks0 = 0; ks0 < 4; ks0++) {
            unsigned kstep = ((unsigned)ks0 + kphase) & 3u;
            unsigned kb = ((kstep * 32u) + hsel) ^ key;
            unsigned a[2][4];
            #pragma unroll
            for (int mi = 0; mi < 2; mi++)
                ldm4(a[mi][0], a[mi][1], a[mi][2], a[mi][3],
                     base + aOff + mi * 2048u + kb);
            unsigned bf[2][4];
            #pragma unroll
            for (int j = 0; j < 2; j++)
                ldm4(bf[j][0], bf[j][1], bf[j][2], bf[j][3],
                     base + bOff + j * 2048u + kb);
            #pragma unroll
            for (int mi = 0; mi < 2; mi++) {
                #pragma unroll
                for (int j = 0; j < 2; j++) {
                    mma_f16(acc[mi][2 * j],     a[mi][0], a[mi][1], a[mi][2], a[mi][3],
                            bf[j][0], bf[j][2]);
                    mma_f16(acc[mi][2 * j + 1], a[mi][0], a[mi][1], a[mi][2], a[mi][3],
                            bf[j][1], bf[j][3]);
                }
            }
        }
    };

    auto store_uv = [&](int gi) {
        __half* Mu = g_M + ((((size_t)apair * 16 + uvq * 4 + gi) * 2 + thalf) * 128) * 256;
        #pragma unroll
        for (int mi = 0; mi < 2; mi++) {
            int m0 = warp_m * 32 + mi * 16 + g;
            #pragma unroll
            for (int ni = 0; ni < 4; ni++) {
                int n = warp_n * 32 + ni * 8 + 2 * q;
                *(__half2*)(Mu + (size_t)m0 * 256 + n) =
                    __floats2half2_rn(acc[mi][ni][0], acc[mi][ni][1]);
                *(__half2*)(Mu + (size_t)(m0 + 8) * 256 + n) =
                    __floats2half2_rn(acc[mi][ni][2], acc[mi][ni][3]);
                acc[mi][ni][0] = acc[mi][ni][1] = acc[mi][ni][2] = acc[mi][ni][3] = 0.f;
            }
        }
    };

    load_stage(0, 0);
    load_stage(1, 1);
    for (int i = 0; i < NITER; i += 2) {
        asm volatile("cp.async.wait_group 0;" ::: "memory");
        __syncthreads();
        if (i + 2 < NITER) load_stage(i + 2, (i + 2) & 3);
        if (i + 3 < NITER) load_stage(i + 3, (i + 3) & 3);
        compute(i & 3);
        compute((i + 1) & 3);
        if (!is_shared && (i & 3) == 2) store_uv(i >> 2);
    }
    if (!is_shared) return;

    {
        float s = 0.f, sq = 0.f;
        #pragma unroll
        for (int mi = 0; mi < 2; mi++)
            #pragma unroll
            for (int ni = 0; ni < 4; ni++)
                #pragma unroll
                for (int c = 0; c < 4; c++) {
                    float v = acc[mi][ni][c];
                    s += v;
                    sq = fmaf(v, v, sq);
                }
        s = warpsum(s); sq = warpsum(sq);
        if (lane == 0) {
            int idx = ((slot_b * GG + warp_n) * 4 + warp_m) * 8 + pxtile;
            g_psum[idx] = s;
            g_psq[idx]  = sq;
        }
    }
    __syncthreads();

    float* T = (float*)smem;
    #pragma unroll
    for (int mi = 0; mi < 2; mi++) {
        int m = warp_m * 32 + mi * 16 + g;
        #pragma unroll
        for (int ni = 0; ni < 4; ni++) {
            int n = warp_n * 32 + ni * 8 + 2 * q;
            T[n * 132 + m]           = acc[mi][ni][0];
            T[(n + 1) * 132 + m]     = acc[mi][ni][1];
            T[n * 132 + m + 8]       = acc[mi][ni][2];
            T[(n + 1) * 132 + m + 8] = acc[mi][ni][3];
        }
    }
    __syncthreads();

    #pragma unroll
    for (int rr = 0; rr < 8; rr++) {
        int n = warp * 8 + rr;
        float4 v = *(const float4*)(T + n * 132 + lane * 4);
        __half2 h01 = __floats2half2_rn(v.x, v.y);
        __half2 h23 = __floats2half2_rn(v.z, v.w);
        uint2 u;
        u.x = *(unsigned*)&h01;
        u.y = *(unsigned*)&h23;
        *(uint2*)(sh_out + (size_t)n * HWSZ + sh_p0 + lane * 4) = u;
    }
}

// ---------------- K4: output transform + expert GN stats + shared finalize -----
__global__ void outfin_kernel() {
    extern __shared__ __half Ybuf[];          // [32][YST]
    __shared__ float ss[8], sqs[8];
    int bid = blockIdx.x;
    int tid = threadIdx.x, w = tid >> 5, lane = tid & 31;

    if (bid >= 256) {
        int item = (bid - 256) * 8 + w;        // 0..127
        if (item >= BB * GG) return;
        int slot = item / GG, g = item % GG;
        int base = (slot * GG + g) * 32;
        float S = warpsum(g_psum[base + lane]);
        float Q = warpsum(g_psq[base + lane]);
        if (lane == 0) {
            const float inv = 1.0f / (CPG * HWSZ);
            float mean = S * inv;
            float var = Q * inv - mean * mean;
            g_sh_mean[slot * GG + g] = mean;
            g_sh_rstd[slot * GG + g] = rsqrtf(var + EPSV);
        }
        return;
    }

    int apair = bid >> 3, grp = bid & 7;
    if (apair >= g_nact) return;
    int be = g_actlist[apair];

    int opl = lane & 15, tsub = lane >> 4;
    int o_loc = 2 * opl;
    int o = grp * CPG + o_loc;
    const __half* Mb = g_M + (size_t)apair * 16 * 2 * 128 * 256;

    float s = 0.f, sq = 0.f;
    for (int tt = 0; tt < 16; tt++) {
        int t = w * 32 + tsub * 16 + tt;
        int tl = t & 127, th2 = t >> 7;
        float2 Mv[16];
        #pragma unroll
        for (int uv = 0; uv < 16; uv++) {
            __half2 h = *(const __half2*)(Mb + (((size_t)uv * 2 + th2) * 128 + tl) * 256 + o);
            Mv[uv] = __half22float2(h);
        }
        float zm0x[4], zm1x[4], zm0y[4], zm1y[4];
        #pragma unroll
        for (int j = 0; j < 4; j++) {
            zm0x[j] = Mv[j].x + Mv[4 + j].x + Mv[8 + j].x;
            zm1x[j] = Mv[4 + j].x - Mv[8 + j].x - Mv[12 + j].x;
            zm0y[j] = Mv[j].y + Mv[4 + j].y + Mv[8 + j].y;
            zm1y[j] = Mv[4 + j].y - Mv[8 + j].y - Mv[12 + j].y;
        }
        float y00x = zm0x[0] + zm0x[1] + zm0x[2];
        float y01x = zm0x[1] - zm0x[2] - zm0x[3];
        float y10x = zm1x[0] + zm1x[1] + zm1x[2];
        float y11x = zm1x[1] - zm1x[2] - zm1x[3];
        float y00y = zm0y[0] + zm0y[1] + zm0y[2];
        float y01y = zm0y[1] - zm0y[2] - zm0y[3];
        float y10y = zm1y[0] + zm1y[1] + zm1y[2];
        float y11y = zm1y[1] - zm1y[2] - zm1y[3];

        s += y00x + y01x + y10x + y11x + y00y + y01y + y10y + y11y;
        sq = fmaf(y00x, y00x, sq); sq = fmaf(y01x, y01x, sq);
        sq = fmaf(y10x, y10x, sq); sq = fmaf(y11x, y11x, sq);
        sq = fmaf(y00y, y00y, sq); sq = fmaf(y01y, y01y, sq);
        sq = fmaf(y10y, y10y, sq); sq = fmaf(y11y, y11y, sq);

        int th = t >> 4, tw = t & 15;
        int px = th * 64 + 2 * tw;
        *(__half2*)&Ybuf[o_loc * YST + px]            = __floats2half2_rn(y00x, y01x);
        *(__half2*)&Ybuf[o_loc * YST + px + 32]       = __floats2half2_rn(y10x, y11x);
        *(__half2*)&Ybuf[(o_loc + 1) * YST + px]      = __floats2half2_rn(y00y, y01y);
        *(__half2*)&Ybuf[(o_loc + 1) * YST + px + 32] = __floats2half2_rn(y10y, y11y);
    }
    s = warpsum(s); sq = warpsum(sq);
    if (lane == 0) { ss[w] = s; sqs[w] = sq; }
    __syncthreads();
    if (tid == 0) {
        float S = 0.f, Q = 0.f;
        #pragma unroll
        for (int i = 0; i < 8; i++) { S += ss[i]; Q += sqs[i]; }
        const float inv = 1.0f / (CPG * HWSZ);
        float mean = S * inv;
        float var = Q * inv - mean * mean;
        g_ex_mean[be * GG + grp] = mean;
        g_ex_rstd[be * GG + grp] = rsqrtf(var + EPSV);
    }
    __half* outb = g_expert_raw + ((size_t)be * OO + grp * CPG) * HWSZ;
    for (int idx = tid; idx < 32 * 512; idx += 256) {
        int row = idx >> 9, c = idx & 511;
        unsigned v = *(unsigned*)&Ybuf[row * YST + c * 2];
        ((unsigned*)(outb + (size_t)row * HWSZ))[c] = v;
    }
}

// ---------------- K5: normalize + SiLU + gated combine (half4 loads) -----------
__global__ void combine_kernel(const float* __restrict__ egam, const float* __restrict__ ebet,
                               const float* __restrict__ sgam, const float* __restrict__ sbet,
                               float* __restrict__ out) {
    size_t i4 = (size_t)blockIdx.x * 256 + threadIdx.x;
    size_t t = i4 >> 8;
    int o = (int)(t & 255);
    int b = (int)(t >> 8);
    int g = o >> 5;

    uint2 vv = ((const uint2*)g_shared_raw)[i4];
    __half2 v01 = *(__half2*)&vv.x, v23 = *(__half2*)&vv.y;
    float2 f01 = __half22float2(v01), f23 = __half22float2(v23);
    float m = g_sh_mean[b * GG + g], r = g_sh_rstd[b * GG + g];
    float ga = sgam[o], be_ = sbet[o];
    float4 res;
    res.x = silu(fmaf((f01.x - m) * r, ga, be_));
    res.y = silu(fmaf((f01.y - m) * r, ga, be_));
    res.z = silu(fmaf((f23.x - m) * r, ga, be_));
    res.w = silu(fmaf((f23.y - m) * r, ga, be_));

    #pragma unroll
    for (int e = 0; e < EE; e++) {
        float ge = g_gate[b * EE + e];
        if (ge != 0.f) {
            int beg = b * EE + e;
            size_t ei = ((size_t)beg * OO + o) * (HWSZ / 4) + (i4 & 255);
            uint2 ew2 = ((const uint2*)g_expert_raw)[ei];
            __half2 e01 = *(__half2*)&ew2.x, e23 = *(__half2*)&ew2.y;
            float2 g01 = __half22float2(e01), g23 = __half22float2(e23);
            float em = g_ex_mean[beg * GG + g], er = g_ex_rstd[beg * GG + g];
            float eg = egam[e * OO + o], eb = ebet[e * OO + o];
            res.x = fmaf(ge, silu(fmaf((g01.x - em) * er, eg, eb)), res.x);
            res.y = fmaf(ge, silu(fmaf((g01.y - em) * er, eg, eb)), res.y);
            res.z = fmaf(ge, silu(fmaf((g23.x - em) * er, eg, eb)), res.z);
            res.w = fmaf(ge, silu(fmaf((g23.y - em) * er, eg, eb)), res.w);
        }
    }
    ((float4*)out)[i4] = res;
}

// ---------------- launch ------------------------------------------------------
extern "C" void kernel_launch(void* const* d_in, const int* in_sizes, int n_in,
                              void* d_out, int out_size) {
    const float* x    = (const float*)d_in[0];
    const float* rw1  = (const float*)d_in[1];
    const float* rb1  = (const float*)d_in[2];
    const float* rw2  = (const float*)d_in[3];
    const float* rb2  = (const float*)d_in[4];
    const float* ew   = (const float*)d_in[5];
    const float* egam = (const float*)d_in[6];
    const float* ebet = (const float*)d_in[7];
    const float* sw   = (const float*)d_in[8];
    const float* sgam = (const float*)d_in[9];
    const float* sbet = (const float*)d_in[10];
    float* out = (float*)d_out;

    cudaFuncSetAttribute(gemm_kernel, cudaFuncAttributeMaxDynamicSharedMemorySize, SMEM_TOTAL);
    cudaFuncSetAttribute(outfin_kernel, cudaFuncAttributeMaxDynamicSharedMemorySize, YBUF_BYTES);

    prep_kernel<<<1824, 256>>>(x, sw, ew);
    vtrans_kernel<<<272, 256>>>();
    router_kernel<<<1, 256>>>(rw1, rb1, rw2, rb2);
    gemm_kernel<<<384, 1024, SMEM_TOTAL>>>();
    outfin_kernel<<<272, 256, YBUF_BYTES>>>();
    combine_kernel<<<(BB * OO * HWSZ / 4) / 256, 256>>>(egam, ebet, sgam, sbet, out);
}